// round 9
// baseline (speedup 1.0000x reference)
#include <cuda_runtime.h>
#include <cuda_fp16.h>
#include <cstdint>

// LaplacianReg: B=32, V=65536, K=8, C=3
// result[b,v,c] = (d[b,v,c] + sum_k w[v,k]*d[b,idx[v,k],c])^2,  d = out - tgt
//
// fp16 scratch [v][c][b], rows padded to 256B (128-aligned -> every gather row
// = exactly 2 L1 lines). Pass 2: 2 v per warp, cp.async row gathers, mixed
// fma.rn.f32.f16 accumulation (no explicit converts), smem-staged output.

#define BB 32
#define VV 65536
#define CC 3
#define KK 8
#define ROWQ 12        // payload uint4 per v (192B)
#define ROWP 16        // padded row stride in uint4 (256B)
#define TILE_V 64
#define P1PAD 104      // pass-1 smem halfs per v row
#define P2PAD 100      // pass-2 smem floats per v row
#define SLOT 384       // stage bytes per k-slot (2 rows' payload)

// 16.8 MB fp16 scratch (padded rows), uint4 for 16B alignment
__device__ uint4 g_diff_raw[(size_t)VV * ROWP];

__device__ __forceinline__ float ffma_h(float acc, __half a, __half b) {
    float r;
    unsigned short ua = *(unsigned short*)&a;
    unsigned short ub = *(unsigned short*)&b;
    asm("fma.rn.f32.f16 %0, %1, %2, %3;"
        : "=f"(r) : "h"(ua), "h"(ub), "f"(acc));
    return r;
}

// ---------------- Pass 1: diff + fp16 convert + transpose ----------------
__global__ void __launch_bounds__(256) diff_transpose_kernel(
    const float* __restrict__ out_, const float* __restrict__ tgt_)
{
    __shared__ __half s[TILE_V * P1PAD];

    const int tid = threadIdx.x;
    const int v0  = blockIdx.x * TILE_V;

#pragma unroll
    for (int it = 0; it < 6; it++) {
        int r4   = tid + it * 256;          // 0..1535
        int b    = r4 / 48;
        int off4 = r4 - b * 48;
        const float4* o4 = (const float4*)(out_ + (size_t)b * (VV * CC) + (size_t)v0 * CC);
        const float4* t4 = (const float4*)(tgt_ + (size_t)b * (VV * CC) + (size_t)v0 * CC);
        float4 o = o4[off4];
        float4 t = t4[off4];
        float d[4] = { o.x - t.x, o.y - t.y, o.z - t.z, o.w - t.w };
        int off = off4 * 4;                 // 0..191 = v_local*3 + c
#pragma unroll
        for (int j = 0; j < 4; j++) {
            int oo = off + j;
            int vl = oo / 3;
            int c  = oo - vl * 3;
            s[vl * P1PAD + c * 32 + b] = __float2half_rn(d[j]);
        }
    }
    __syncthreads();

    // write payload (12 uint4 per row) at padded stride 16
    uint4* gout = g_diff_raw + (size_t)v0 * ROWP;
#pragma unroll
    for (int it = 0; it < 3; it++) {
        int f   = tid + it * 256;           // 0..767
        int vl  = f / ROWQ;
        int off = f - vl * ROWQ;
        gout[vl * ROWP + off] = *(const uint4*)(s + vl * P1PAD + off * 8);
    }
}

// ---------------- Pass 2: cp.async gather + mixed-fma accumulate -----------
// block 256 = 8 warps; warp handles 2 v; block handles 16 v.
__global__ void __launch_bounds__(256) lap_kernel(
    const int* __restrict__ nidx, const float* __restrict__ nw,
    float* __restrict__ res)
{
    __shared__ __align__(16) char stage[8 * KK * SLOT];   // 24576 B
    __shared__ float  s[16 * P2PAD];
    __shared__ int    si[128];
    __shared__ __half swh[128];

    const int tid = threadIdx.x;
    const int v0  = blockIdx.x * 16;

    if (tid < 128) {
        si[tid] = nidx[v0 * KK + tid];
    } else {
        swh[tid - 128] = __float2half_rn(nw[v0 * KK + (tid - 128)]);
    }
    __syncthreads();

    const int lane = tid & 31;
    const int wrp  = tid >> 5;

    if (lane < 24) {
        const int g   = lane >= 12 ? 1 : 0;
        const int sub = lane - g * 12;
        const int vl  = wrp * 2 + g;        // 0..15
        const int v   = v0 + vl;

        // fire 8 neighbor-row copies, 16B per lane, no dest registers
        unsigned int sb = (unsigned int)__cvta_generic_to_shared(stage)
                          + wrp * (KK * SLOT) + g * 192 + sub * 16;
        const int* ip = si + vl * KK;
#pragma unroll
        for (int k = 0; k < KK; k++) {
            int nk = ip[k];
            const void* src = (const void*)(g_diff_raw + (size_t)nk * ROWP + sub);
            unsigned int dst = sb + k * SLOT;
            asm volatile("cp.async.cg.shared.global [%0], [%1], 16;\n"
                         :: "r"(dst), "l"(src));
        }
        asm volatile("cp.async.commit_group;\n");

        // self row (weight 1): 12 lanes x uint4 = one padded row, 2 lines
        uint4 r = __ldg(g_diff_raw + (size_t)v * ROWP + sub);
        const __half* rh = (const __half*)&r;
        float a0 = __half2float(rh[0]);
        float a1 = __half2float(rh[1]);
        float a2 = __half2float(rh[2]);
        float a3 = __half2float(rh[3]);
        float a4 = __half2float(rh[4]);
        float a5 = __half2float(rh[5]);
        float a6 = __half2float(rh[6]);
        float a7 = __half2float(rh[7]);

        asm volatile("cp.async.wait_group 0;\n");

        const __half* wp = swh + vl * KK;
        const char*   rb = stage + wrp * (KK * SLOT) + g * 192 + sub * 16;
#pragma unroll
        for (int k = 0; k < KK; k++) {
            __half wk = wp[k];
            uint4  q  = *(const uint4*)(rb + k * SLOT);
            const __half* qh = (const __half*)&q;
            a0 = ffma_h(a0, qh[0], wk);
            a1 = ffma_h(a1, qh[1], wk);
            a2 = ffma_h(a2, qh[2], wk);
            a3 = ffma_h(a3, qh[3], wk);
            a4 = ffma_h(a4, qh[4], wk);
            a5 = ffma_h(a5, qh[5], wk);
            a6 = ffma_h(a6, qh[6], wk);
            a7 = ffma_h(a7, qh[7], wk);
        }

        float4 w1 = { a0 * a0, a1 * a1, a2 * a2, a3 * a3 };
        float4 w2 = { a4 * a4, a5 * a5, a6 * a6, a7 * a7 };
        *(float4*)(s + vl * P2PAD + sub * 8)     = w1;
        *(float4*)(s + vl * P2PAD + sub * 8 + 4) = w2;
    }
    __syncthreads();

    // output (B,V,C): thread -> b = tid/8, vq = tid%8; two v per thread
    const int b  = tid >> 3;
    const int vq = tid & 7;
#pragma unroll
    for (int h = 0; h < 2; h++) {
        int vl = vq + h * 8;
        const float* sr = s + vl * P2PAD + b;
        float r0 = sr[0];
        float r1 = sr[32];
        float r2 = sr[64];
        float* op = res + (size_t)b * (VV * CC) + (size_t)(v0 + vl) * CC;
        op[0] = r0;
        op[1] = r1;
        op[2] = r2;
    }
}

extern "C" void kernel_launch(void* const* d_in, const int* in_sizes, int n_in,
                              void* d_out, int out_size)
{
    const float* out_ = (const float*)d_in[0];
    const float* tgt_ = (const float*)d_in[1];
    const int*   nidx = (const int*)  d_in[2];
    const float* nw   = (const float*)d_in[3];
    float*       res  = (float*)d_out;

    diff_transpose_kernel<<<VV / TILE_V, 256>>>(out_, tgt_);
    lap_kernel<<<VV / 16, 256>>>(nidx, nw, res);
}